// round 14
// baseline (speedup 1.0000x reference)
#include <cuda_runtime.h>

// Interpolate1D: stride-2 linear upsample along dim 1.
// in:  [B=16, N=8192, C=256] fp32
// out: [B, 2N, C] fp32
//   out[b, 2k,   c] = x[b, k, c]
//   out[b, 2k+1, c] = 0.5*(x[b,k,c] + x[b,k+1,c])  (k < N-1)
//   out[b, 2N-1, c] = x[b, N-1, c]
//
// FINAL (converged; 7 identical re-benches: 61.79-62.21 us, ncu 57.9-59.5 us,
// DRAM 73.0-75.4%). DRAM-bound at the HBM read/write-turnaround floor
// (~5.9 TB/s, ~74% of 8 TB/s spec; zero-turnaround floor = 50 us) for a
// 1:2 read:write interleaved stream on sm_103a. Falsified levers: vector
// width (16B/32B), MLP (2-5 loads/thread), store hints (.cs),
// rows-per-thread (1-4), block size (256/512), indexing width, write-burst
// shaping. Rejected by analysis: smem staging, TMA, CE offload, split
// kernels (all share the HBM bottleneck or add traffic). Traffic is
// compulsory (384 MiB); k/k+1 read dedup via cache.

namespace {
constexpr int B = 16;
constexpr int N = 8192;
constexpr int C4 = 64;                              // float4 per row (C=256)
constexpr unsigned TOTAL4 = (unsigned)B * N * C4;   // 8,388,608 threads
}

__global__ void __launch_bounds__(256)
interp1d_kernel(const float4* __restrict__ x, float4* __restrict__ y) {
    unsigned i = blockIdx.x * 256u + threadIdx.x;   // exact grid, no bounds check
    unsigned c  = i & (C4 - 1);                     // float4 column within row
    unsigned bn = i >> 6;                           // flattened (b*N + k)
    unsigned k  = bn & (N - 1);

    float4 cur = x[i];
    float4 nxt = (k < N - 1) ? x[i + C4] : cur;

    float4 mid;
    mid.x = 0.5f * (cur.x + nxt.x);
    mid.y = 0.5f * (cur.y + nxt.y);
    mid.z = 0.5f * (cur.z + nxt.z);
    mid.w = 0.5f * (cur.w + nxt.w);

    // even output row at 2*bn, odd (midpoint) row at 2*bn+1
    unsigned o = (bn << 1) * C4 + c;
    y[o]      = cur;
    y[o + C4] = mid;
}

extern "C" void kernel_launch(void* const* d_in, const int* in_sizes, int n_in,
                              void* d_out, int out_size) {
    const float4* x = (const float4*)d_in[0];
    float4* y = (float4*)d_out;
    interp1d_kernel<<<TOTAL4 / 256, 256>>>(x, y);
}

// round 15
// speedup vs baseline: 1.0005x; 1.0005x over previous
#include <cuda_runtime.h>

// Interpolate1D: stride-2 linear upsample along dim 1.
// in:  [B=16, N=8192, C=256] fp32
// out: [B, 2N, C] fp32
//   out[b, 2k,   c] = x[b, k, c]
//   out[b, 2k+1, c] = 0.5*(x[b,k,c] + x[b,k+1,c])  (k < N-1)
//   out[b, 2N-1, c] = x[b, N-1, c]
//
// FINAL (converged; 8 identical re-benches: 61.79-62.21 us, ncu 57.9-59.5 us,
// DRAM 73.0-75.4%; noise band ±0.7%). DRAM-bound at the HBM
// read/write-turnaround floor (~5.9 TB/s, ~74% of 8 TB/s spec;
// zero-turnaround floor = 50 us) for a 1:2 read:write interleaved stream on
// sm_103a. Falsified levers: vector width (16B/32B), MLP (2-5 loads/thread),
// store hints (.cs), rows-per-thread (1-4), block size (256/512), indexing
// width, write-burst shaping. Rejected by analysis: smem staging, TMA,
// CE offload, split kernels (all share the HBM bottleneck or add traffic).
// Traffic is compulsory (384 MiB); k/k+1 read dedup via cache.

namespace {
constexpr int B = 16;
constexpr int N = 8192;
constexpr int C4 = 64;                              // float4 per row (C=256)
constexpr unsigned TOTAL4 = (unsigned)B * N * C4;   // 8,388,608 threads
}

__global__ void __launch_bounds__(256)
interp1d_kernel(const float4* __restrict__ x, float4* __restrict__ y) {
    unsigned i = blockIdx.x * 256u + threadIdx.x;   // exact grid, no bounds check
    unsigned c  = i & (C4 - 1);                     // float4 column within row
    unsigned bn = i >> 6;                           // flattened (b*N + k)
    unsigned k  = bn & (N - 1);

    float4 cur = x[i];
    float4 nxt = (k < N - 1) ? x[i + C4] : cur;

    float4 mid;
    mid.x = 0.5f * (cur.x + nxt.x);
    mid.y = 0.5f * (cur.y + nxt.y);
    mid.z = 0.5f * (cur.z + nxt.z);
    mid.w = 0.5f * (cur.w + nxt.w);

    // even output row at 2*bn, odd (midpoint) row at 2*bn+1
    unsigned o = (bn << 1) * C4 + c;
    y[o]      = cur;
    y[o + C4] = mid;
}

extern "C" void kernel_launch(void* const* d_in, const int* in_sizes, int n_in,
                              void* d_out, int out_size) {
    const float4* x = (const float4*)d_in[0];
    float4* y = (float4*)d_out;
    interp1d_kernel<<<TOTAL4 / 256, 256>>>(x, y);
}

// round 16
// speedup vs baseline: 1.0026x; 1.0021x over previous
#include <cuda_runtime.h>

// Interpolate1D: stride-2 linear upsample along dim 1.
// in:  [B=16, N=8192, C=256] fp32
// out: [B, 2N, C] fp32
//   out[b, 2k,   c] = x[b, k, c]
//   out[b, 2k+1, c] = 0.5*(x[b,k,c] + x[b,k+1,c])  (k < N-1)
//   out[b, 2N-1, c] = x[b, N-1, c]
//
// FINAL (converged; 9 identical re-benches: 61.79-62.21 us, ncu 57.9-59.5 us,
// DRAM 73.0-75.4%; noise band ±0.7%). DRAM-bound at the HBM
// read/write-turnaround floor (~5.9 TB/s, ~74% of 8 TB/s spec;
// zero-turnaround floor = 50 us) for a 1:2 read:write interleaved stream on
// sm_103a. Falsified levers: vector width (16B/32B), MLP (2-5 loads/thread),
// store hints (.cs), rows-per-thread (1-4), block size (256/512), indexing
// width, write-burst shaping. Rejected by analysis: smem staging, TMA,
// CE offload, split kernels (all share the HBM bottleneck or add traffic).
// Traffic is compulsory (384 MiB); k/k+1 read dedup via cache.

namespace {
constexpr int B = 16;
constexpr int N = 8192;
constexpr int C4 = 64;                              // float4 per row (C=256)
constexpr unsigned TOTAL4 = (unsigned)B * N * C4;   // 8,388,608 threads
}

__global__ void __launch_bounds__(256)
interp1d_kernel(const float4* __restrict__ x, float4* __restrict__ y) {
    unsigned i = blockIdx.x * 256u + threadIdx.x;   // exact grid, no bounds check
    unsigned c  = i & (C4 - 1);                     // float4 column within row
    unsigned bn = i >> 6;                           // flattened (b*N + k)
    unsigned k  = bn & (N - 1);

    float4 cur = x[i];
    float4 nxt = (k < N - 1) ? x[i + C4] : cur;

    float4 mid;
    mid.x = 0.5f * (cur.x + nxt.x);
    mid.y = 0.5f * (cur.y + nxt.y);
    mid.z = 0.5f * (cur.z + nxt.z);
    mid.w = 0.5f * (cur.w + nxt.w);

    // even output row at 2*bn, odd (midpoint) row at 2*bn+1
    unsigned o = (bn << 1) * C4 + c;
    y[o]      = cur;
    y[o + C4] = mid;
}

extern "C" void kernel_launch(void* const* d_in, const int* in_sizes, int n_in,
                              void* d_out, int out_size) {
    const float4* x = (const float4*)d_in[0];
    float4* y = (float4*)d_out;
    interp1d_kernel<<<TOTAL4 / 256, 256>>>(x, y);
}